// round 7
// baseline (speedup 1.0000x reference)
#include <cuda_runtime.h>
#include <cuda_bf16.h>
#include <cstdint>

#define B_SZ  16
#define D_SZ  384
#define N_SZ  8192
#define KV_M  1024      // k rows 0..511, v rows 512..1023
#define HEADS 8
#define LN_EPS 1e-5f
#define Q_SCALE 0.125f  // 64^-0.5
#define BP_STRIDE 136   // padded bf16 stride for 128-col panel (272B = 17x16B)
#define AS_STRIDE 40    // padded bf16 stride for 32-col A tile (80B = 5x16B)
#define CS_STRIDE 72    // padded bf16 stride for 64-col ctx tiles (144B = 9x16B)
#define NTILES (N_SZ / 128)   // 64

// ---------------- scratch (static device globals: allocation-free) ----------
__device__ __nv_bfloat16 g_xn[(size_t)B_SZ * D_SZ * N_SZ];     // 100 MB normalized x (bf16)
__device__ __nv_bfloat16 g_kv[(size_t)B_SZ * KV_M * N_SZ];     // 268 MB raw K,V
__device__ __nv_bfloat16 g_wkv[KV_M * D_SZ];                    // bf16 copy of w_qkv rows 512..1535
__device__ float         g_pmx[(size_t)B_SZ * 512 * NTILES];    // per-(row,ntile) max partials
__device__ float         g_pse[(size_t)B_SZ * 512 * NTILES];    // per-(row,ntile) sum-exp partials
__device__ float         g_rowmx[B_SZ * 512];
__device__ float         g_rowinv[B_SZ * 512];
__device__ float         g_ctx_part[8][B_SZ * HEADS * 64 * 64]; // split-K partials (16 MB)
__device__ float         g_ctx[B_SZ * HEADS * 64 * 64];
__device__ float         g_W2[(size_t)B_SZ * 384 * 512];
__device__ __nv_bfloat16 g_W3[(size_t)B_SZ * 384 * 384];

// ---------------- mma / ldmatrix helpers ------------------------------------
__device__ __forceinline__ uint32_t smem_u32(const void* p) {
    return (uint32_t)__cvta_generic_to_shared(p);
}
__device__ __forceinline__ void ldsm_x4(uint32_t& r0, uint32_t& r1, uint32_t& r2, uint32_t& r3, uint32_t a) {
    asm volatile("ldmatrix.sync.aligned.m8n8.x4.shared.b16 {%0,%1,%2,%3},[%4];\n"
                 : "=r"(r0), "=r"(r1), "=r"(r2), "=r"(r3) : "r"(a));
}
__device__ __forceinline__ void ldsm_x2(uint32_t& r0, uint32_t& r1, uint32_t a) {
    asm volatile("ldmatrix.sync.aligned.m8n8.x2.shared.b16 {%0,%1},[%2];\n"
                 : "=r"(r0), "=r"(r1) : "r"(a));
}
__device__ __forceinline__ void ldsm_x2_t(uint32_t& r0, uint32_t& r1, uint32_t a) {
    asm volatile("ldmatrix.sync.aligned.m8n8.x2.trans.shared.b16 {%0,%1},[%2];\n"
                 : "=r"(r0), "=r"(r1) : "r"(a));
}
__device__ __forceinline__ void mma16816(float c[4], uint32_t a0, uint32_t a1, uint32_t a2, uint32_t a3,
                                         uint32_t b0, uint32_t b1) {
    asm volatile("mma.sync.aligned.m16n8k16.row.col.f32.bf16.bf16.f32 "
                 "{%0,%1,%2,%3},{%4,%5,%6,%7},{%8,%9},{%0,%1,%2,%3};\n"
                 : "+f"(c[0]), "+f"(c[1]), "+f"(c[2]), "+f"(c[3])
                 : "r"(a0), "r"(a1), "r"(a2), "r"(a3), "r"(b0), "r"(b1));
}
// exp((k - mx)) * inv applied to 8 bf16 values packed in a uint4
__device__ __forceinline__ uint4 expk4(uint4 raw, float mx, float inv) {
    __nv_bfloat162* h2 = (__nv_bfloat162*)&raw;
    uint4 outp;
    __nv_bfloat162* o2 = (__nv_bfloat162*)&outp;
#pragma unroll
    for (int j = 0; j < 4; j++) {
        float2 f = __bfloat1622float2(h2[j]);
        o2[j] = __floats2bfloat162_rn(__expf(f.x - mx) * inv, __expf(f.y - mx) * inv);
    }
    return outp;
}

// ---------------- kernel 1: convert KV weights to bf16 ----------------------
__global__ __launch_bounds__(256) void k_prep(const float* __restrict__ w_qkv) {
    int i = blockIdx.x * 256 + threadIdx.x;
    if (i < KV_M * D_SZ) g_wkv[i] = __float2bfloat16(w_qkv[512 * D_SZ + i]);
}

// ---------------- kernel 2: single-pass layernorm via smem tile --------------
__global__ __launch_bounds__(256) void k_lnxn(const float* __restrict__ x,
                                              const float* __restrict__ gamma,
                                              const float* __restrict__ beta) {
    extern __shared__ __align__(16) float tile[];      // 384*33 floats
    __shared__ float sred[8][32], qred[8][32];
    __shared__ float mcol[32], rcol[32];
    const int t = threadIdx.x;
    const int n0 = blockIdx.x * 32;
    const int b = blockIdx.y;
    const int col = t & 31, sub = t >> 5;
    const float* xp = x + (size_t)b * D_SZ * N_SZ + n0;

    for (int row = sub; row < D_SZ; row += 8)
        tile[row * 33 + col] = xp[(size_t)row * N_SZ + col];
    __syncthreads();

    float s = 0.f, q = 0.f;
    for (int row = sub; row < D_SZ; row += 8) {
        float v = tile[row * 33 + col];
        s += v; q += v * v;
    }
    sred[sub][col] = s; qred[sub][col] = q;
    __syncthreads();
    if (t < 32) {
        float ss = 0.f, qq = 0.f;
#pragma unroll
        for (int i = 0; i < 8; i++) { ss += sred[i][t]; qq += qred[i][t]; }
        const float inv_d = 1.f / D_SZ;
        float m = ss * inv_d;
        mcol[t] = m;
        rcol[t] = rsqrtf(qq * inv_d - m * m + LN_EPS);
    }
    __syncthreads();

    const float m = mcol[col], r = rcol[col];
    __nv_bfloat16* op = g_xn + (size_t)b * D_SZ * N_SZ + n0;
    for (int row = sub; row < D_SZ; row += 8) {
        float gd = gamma[row], bd = beta[row];
        op[(size_t)row * N_SZ + col] = __float2bfloat16((tile[row * 33 + col] - m) * r * gd + bd);
    }
}

// ---------------- kernel 3: KV GEMM, B-panel resident, fused K row stats -----
__global__ __launch_bounds__(256) void k_gemm_kv() {
    extern __shared__ __align__(16) char dyn[];
    __nv_bfloat16* Bp = (__nv_bfloat16*)dyn;                                  // 384 x 136
    __nv_bfloat16* As = (__nv_bfloat16*)(dyn + D_SZ * BP_STRIDE * 2);         // 2 x 128 x 40
    const int t  = threadIdx.x;
    const int b  = blockIdx.y;
    const int ntile = blockIdx.x;
    const int n0 = ntile * 128;
    const int wid = t >> 5, lane = t & 31;
    const int wm = wid >> 2, wn = wid & 3;

    const __nv_bfloat16* Bg = g_xn + (size_t)b * D_SZ * N_SZ;
#pragma unroll
    for (int u = t; u < D_SZ * 16; u += 256) {
        int row = u >> 4, c8 = (u & 15) * 8;
        *(uint4*)(Bp + row * BP_STRIDE + c8) = *(const uint4*)(Bg + (size_t)row * N_SZ + n0 + c8);
    }

    const int ar0 = t >> 2,         ac0 = (t & 3) * 8;
    const int ar1 = (t + 256) >> 2, ac1 = ((t + 256) & 3) * 8;
    const int KSTEPS = D_SZ / 32;   // 12

    for (int mt = 0; mt < KV_M / 128; mt++) {
        const int m0 = mt * 128;
        uint4 a0 = *(const uint4*)(g_wkv + (m0 + ar0) * D_SZ + ac0);
        uint4 a1 = *(const uint4*)(g_wkv + (m0 + ar1) * D_SZ + ac1);
        __syncthreads();   // B panel ready (mt=0) / prev m-tile smem users drained
        *(uint4*)(As + ar0 * AS_STRIDE + ac0) = a0;
        *(uint4*)(As + ar1 * AS_STRIDE + ac1) = a1;
        __syncthreads();

        float acc[4][4][4];
#pragma unroll
        for (int i = 0; i < 4; i++)
#pragma unroll
            for (int j = 0; j < 4; j++)
#pragma unroll
                for (int r = 0; r < 4; r++) acc[i][j][r] = 0.f;

        int s = 0;
        for (int k = 0; k < KSTEPS; k++) {
            if (k + 1 < KSTEPS) {
                int kn = (k + 1) * 32;
                a0 = *(const uint4*)(g_wkv + (m0 + ar0) * D_SZ + kn + ac0);
                a1 = *(const uint4*)(g_wkv + (m0 + ar1) * D_SZ + kn + ac1);
            }
            const __nv_bfloat16* Ab = As + s * (128 * AS_STRIDE);
            const __nv_bfloat16* Bb = Bp + (k * 32) * BP_STRIDE;
#pragma unroll
            for (int kt = 0; kt < 2; kt++) {
                uint32_t a[4][4];
                int lrow = lane & 15, lcol = kt * 16 + (lane >> 4) * 8;
#pragma unroll
                for (int i = 0; i < 4; i++)
                    ldsm_x4(a[i][0], a[i][1], a[i][2], a[i][3],
                            smem_u32(Ab + (wm * 64 + i * 16 + lrow) * AS_STRIDE + lcol));
                uint32_t bb[4][2];
                int l = lane & 15;
#pragma unroll
                for (int j = 0; j < 4; j++)
                    ldsm_x2_t(bb[j][0], bb[j][1],
                              smem_u32(Bb + (kt * 16 + l) * BP_STRIDE + wn * 32 + j * 8));
#pragma unroll
                for (int i = 0; i < 4; i++)
#pragma unroll
                    for (int j = 0; j < 4; j++)
                        mma16816(acc[i][j], a[i][0], a[i][1], a[i][2], a[i][3], bb[j][0], bb[j][1]);
            }
            if (k + 1 < KSTEPS) {
                int ns = s ^ 1;
                __nv_bfloat16* An = As + ns * (128 * AS_STRIDE);
                *(uint4*)(An + ar0 * AS_STRIDE + ac0) = a0;
                *(uint4*)(An + ar1 * AS_STRIDE + ac1) = a1;
                __syncthreads();
                s = ns;
            }
        }
        // store C tile (bf16)
#pragma unroll
        for (int i = 0; i < 4; i++)
#pragma unroll
            for (int j = 0; j < 4; j++) {
                int row = m0 + wm * 64 + i * 16 + (lane >> 2);
                int col = n0 + wn * 32 + j * 8 + (lane & 3) * 2;
                __nv_bfloat162 v01 = __floats2bfloat162_rn(acc[i][j][0], acc[i][j][1]);
                __nv_bfloat162 v23 = __floats2bfloat162_rn(acc[i][j][2], acc[i][j][3]);
                *(__nv_bfloat162*)(g_kv + ((size_t)b * KV_M + row) * N_SZ + col)     = v01;
                *(__nv_bfloat162*)(g_kv + ((size_t)b * KV_M + row + 8) * N_SZ + col) = v23;
            }

        // fused softmax partial stats for K rows (fp32 accs, this CTA's 128 cols)
        if (m0 < 512) {
            float* smax = (float*)As;           // overlay: 128 x 4
            float* ssum = smax + 128 * 4;       // overlay: 128 x 4
            __syncthreads();                    // all warps done reading As this mt
#pragma unroll
            for (int i = 0; i < 4; i++) {
                float mv0 = -3.0e38f, mv1 = -3.0e38f;
#pragma unroll
                for (int j = 0; j < 4; j++) {
                    mv0 = fmaxf(mv0, fmaxf(acc[i][j][0], acc[i][j][1]));
                    mv1 = fmaxf(mv1, fmaxf(acc[i][j][2], acc[i][j][3]));
                }
#pragma unroll
                for (int o = 1; o <= 2; o <<= 1) {
                    mv0 = fmaxf(mv0, __shfl_xor_sync(0xffffffffu, mv0, o));
                    mv1 = fmaxf(mv1, __shfl_xor_sync(0xffffffffu, mv1, o));
                }
                if ((lane & 3) == 0) {
                    int r0 = wm * 64 + i * 16 + (lane >> 2);
                    smax[r0 * 4 + wn]       = mv0;
                    smax[(r0 + 8) * 4 + wn] = mv1;
                }
            }
            __syncthreads();
#pragma unroll
            for (int i = 0; i < 4; i++) {
                int r0 = wm * 64 + i * 16 + (lane >> 2);
                float rm0 = fmaxf(fmaxf(smax[r0 * 4 + 0], smax[r0 * 4 + 1]),
                                  fmaxf(smax[r0 * 4 + 2], smax[r0 * 4 + 3]));
                float rm1 = fmaxf(fmaxf(smax[(r0 + 8) * 4 + 0], smax[(r0 + 8) * 4 + 1]),
                                  fmaxf(smax[(r0 + 8) * 4 + 2], smax[(r0 + 8) * 4 + 3]));
                float s0 = 0.f, s1 = 0.f;
#pragma unroll
                for (int j = 0; j < 4; j++) {
                    s0 += __expf(acc[i][j][0] - rm0) + __expf(acc[i][j][1] - rm0);
                    s1 += __expf(acc[i][j][2] - rm1) + __expf(acc[i][j][3] - rm1);
                }
#pragma unroll
                for (int o = 1; o <= 2; o <<= 1) {
                    s0 += __shfl_xor_sync(0xffffffffu, s0, o);
                    s1 += __shfl_xor_sync(0xffffffffu, s1, o);
                }
                if ((lane & 3) == 0) {
                    ssum[r0 * 4 + wn]       = s0;
                    ssum[(r0 + 8) * 4 + wn] = s1;
                }
            }
            __syncthreads();
            if (t < 128) {
                float rm = fmaxf(fmaxf(smax[t * 4 + 0], smax[t * 4 + 1]),
                                 fmaxf(smax[t * 4 + 2], smax[t * 4 + 3]));
                float sv = ssum[t * 4 + 0] + ssum[t * 4 + 1] + ssum[t * 4 + 2] + ssum[t * 4 + 3];
                size_t idx = ((size_t)(b * 512 + m0 + t)) * NTILES + ntile;
                g_pmx[idx] = rm;
                g_pse[idx] = sv;
            }
        }
    }
}

// ---------------- kernel 4: combine per-ntile stats -> rowmx, rowinv --------
__global__ __launch_bounds__(256) void k_combine() {
    const int w = (blockIdx.x * 256 + threadIdx.x) >> 5;   // global row 0..8191
    const int lane = threadIdx.x & 31;
    const float* pm = g_pmx + (size_t)w * NTILES;
    const float* ps = g_pse + (size_t)w * NTILES;
    float m0 = pm[lane], m1 = pm[lane + 32];
    float m = fmaxf(m0, m1);
#pragma unroll
    for (int o = 16; o > 0; o >>= 1) m = fmaxf(m, __shfl_xor_sync(0xffffffffu, m, o));
    float s = ps[lane] * __expf(m0 - m) + ps[lane + 32] * __expf(m1 - m);
#pragma unroll
    for (int o = 16; o > 0; o >>= 1) s += __shfl_xor_sync(0xffffffffu, s, o);
    if (lane == 0) {
        g_rowmx[w]  = m;
        g_rowinv[w] = 1.f / s;
    }
}

// ---------------- kernel 5: context = softmax(K) @ V^T -----------------------
// 256 threads, 64-col double-buffered steps, register prefetch, exp fused.
__global__ __launch_bounds__(256) void k_ctx() {
    __shared__ __align__(16) __nv_bfloat16 Ks[2][64 * CS_STRIDE];
    __shared__ __align__(16) __nv_bfloat16 Vs[2][64 * CS_STRIDE];
    __shared__ float s_mx[64], s_inv[64];
    const int t = threadIdx.x;
    const int split = blockIdx.x, h = blockIdx.y, b = blockIdx.z;
    const __nv_bfloat16* kp = g_kv + ((size_t)(b * KV_M + h * 64)) * N_SZ;
    const __nv_bfloat16* vp = g_kv + ((size_t)(b * KV_M + 512 + h * 64)) * N_SZ;
    const int wid = t >> 5, lane = t & 31;
    const int wm = wid >> 2, wn = wid & 3;      // 2 x 4 warp grid over 64x64

    if (t < 64) {
        s_mx[t]  = g_rowmx[b * 512 + h * 64 + t];
        s_inv[t] = g_rowinv[b * 512 + h * 64 + t];
    }
    __syncthreads();

    // per-thread load slots: 64 rows x 8 chunks (8 bf16 each) = 512 chunks; 2/thread
    const int r0 = t >> 3,         c0 = (t & 7) * 8;
    const int r1 = (t + 256) >> 3, c1 = ((t + 256) & 7) * 8;
    const float mx0 = s_mx[r0], iv0 = s_inv[r0];
    const float mx1 = s_mx[r1], iv1 = s_inv[r1];

    float acc[2][2][4];
#pragma unroll
    for (int i = 0; i < 2; i++)
#pragma unroll
        for (int j = 0; j < 2; j++)
#pragma unroll
            for (int r = 0; r < 4; r++) acc[i][j][r] = 0.f;

    const int col_base = split * 1024;
    const int STEPS = 16;          // 1024 cols / 64

    // prologue: load step 0
    uint4 ka = *(const uint4*)(kp + (size_t)r0 * N_SZ + col_base + c0);
    uint4 kb = *(const uint4*)(kp + (size_t)r1 * N_SZ + col_base + c1);
    uint4 va = *(const uint4*)(vp + (size_t)r0 * N_SZ + col_base + c0);
    uint4 vb = *(const uint4*)(vp + (size_t)r1 * N_SZ + col_base + c1);
    *(uint4*)(Ks[0] + r0 * CS_STRIDE + c0) = expk4(ka, mx0, iv0);
    *(uint4*)(Ks[0] + r1 * CS_STRIDE + c1) = expk4(kb, mx1, iv1);
    *(uint4*)(Vs[0] + r0 * CS_STRIDE + c0) = va;
    *(uint4*)(Vs[0] + r1 * CS_STRIDE + c1) = vb;
    __syncthreads();

    int s = 0;
    for (int step = 0; step < STEPS; step++) {
        if (step + 1 < STEPS) {
            int kk = col_base + (step + 1) * 64;
            ka = *(const uint4*)(kp + (size_t)r0 * N_SZ + kk + c0);
            kb = *(const uint4*)(kp + (size_t)r1 * N_SZ + kk + c1);
            va = *(const uint4*)(vp + (size_t)r0 * N_SZ + kk + c0);
            vb = *(const uint4*)(vp + (size_t)r1 * N_SZ + kk + c1);
        }
#pragma unroll
        for (int kc = 0; kc < 4; kc++) {        // 4 x k=16 chunks
            uint32_t a[2][4];
            int lrow = lane & 15, lcol = kc * 16 + (lane >> 4) * 8;
#pragma unroll
            for (int i = 0; i < 2; i++)
                ldsm_x4(a[i][0], a[i][1], a[i][2], a[i][3],
                        smem_u32(Ks[s] + (wm * 32 + i * 16 + lrow) * CS_STRIDE + lcol));
            uint32_t bb[2][2];
            int l = lane & 15;
#pragma unroll
            for (int j = 0; j < 2; j++) {
                int e  = wn * 16 + j * 8 + (l & 7);
                int kcc = kc * 16 + (l >> 3) * 8;
                ldsm_x2(bb[j][0], bb[j][1], smem_u32(Vs[s] + e * CS_STRIDE + kcc));
            }
#pragma unroll
            for (int i = 0; i < 2; i++)
#pragma unroll
                for (int j = 0; j < 2; j++)
                    mma16816(acc[i][j], a[i][0], a[i][1], a[i][2], a[i][3], bb[j][0], bb[j][1]);
        }
        if (step + 1 < STEPS) {
            int ns = s ^ 1;
            *(uint4*)(Ks[ns] + r0 * CS_STRIDE + c0) = expk4(ka, mx0, iv0);
            *(uint4*)(Ks[ns] + r1 * CS_STRIDE + c1) = expk4(kb, mx1, iv1);
            *(uint4*)(Vs[ns] + r0 * CS_STRIDE + c0) = va;
            *(uint4*)(Vs[ns] + r1 * CS_STRIDE + c1) = vb;
            __syncthreads();
            s = ns;
        }
    }
    float* dst = g_ctx_part[split] + ((b * HEADS + h) * 64) * 64;
#pragma unroll
    for (int i = 0; i < 2; i++)
#pragma unroll
        for (int j = 0; j < 2; j++) {
            int row = wm * 32 + i * 16 + (lane >> 2);
            int col = wn * 16 + j * 8 + (lane & 3) * 2;
            *(float2*)(dst + row * 64 + col)       = make_float2(acc[i][j][0], acc[i][j][1]);
            *(float2*)(dst + (row + 8) * 64 + col) = make_float2(acc[i][j][2], acc[i][j][3]);
        }
}

__global__ __launch_bounds__(256) void k_ctx_reduce() {
    int i = blockIdx.x * 256 + threadIdx.x;
    if (i < B_SZ * HEADS * 64 * 64) {
        float s = 0.f;
#pragma unroll
        for (int p = 0; p < 8; p++) s += g_ctx_part[p][i];
        g_ctx[i] = s;
    }
}

// ---------------- kernel 6: W2[b][dp][h*64+d] = sum_e w_out[dp][h*64+e]*ctx[b,h,d,e]
__global__ __launch_bounds__(256) void k_w2(const float* __restrict__ w_out) {
    int idx = blockIdx.x * 256 + threadIdx.x;   // 0..196607
    int b = blockIdx.y;
    int dp = idx >> 9;
    int o  = idx & 511;
    int h = o >> 6, d = o & 63;
    const float* wrow = w_out + dp * 512 + h * 64;
    const float* crow = g_ctx + ((b * HEADS + h) * 64 + d) * 64;
    float s = 0.f;
#pragma unroll
    for (int e = 0; e < 64; e++) s += wrow[e] * crow[e];
    g_W2[((size_t)b * 384 + dp) * 512 + o] = s;
}

// ---------------- kernel 7: W3[b] = SCALE * W2[b] @ Wq   (384x384, K=512) ---
__global__ __launch_bounds__(256) void k_w3(const float* __restrict__ w_qkv) {
    __shared__ __align__(16) __nv_bfloat16 As[128 * 40];
    __shared__ __align__(16) __nv_bfloat16 Bs[32 * 136];
    const int t  = threadIdx.x;
    const int b  = blockIdx.z;
    const int m0 = blockIdx.y * 128;
    const int n0 = blockIdx.x * 128;
    const int wid = t >> 5, lane = t & 31;
    const int wm = wid >> 2, wn = wid & 3;
    const float* Wa = g_W2 + (size_t)b * 384 * 512;

    float acc[4][4][4];
#pragma unroll
    for (int i = 0; i < 4; i++)
#pragma unroll
        for (int j = 0; j < 4; j++)
#pragma unroll
            for (int r = 0; r < 4; r++) acc[i][j][r] = 0.f;

    const int r8 = t >> 5;
    const int c4 = t & 31;

    for (int k0 = 0; k0 < 512; k0 += 32) {
        __syncthreads();
#pragma unroll
        for (int u = t; u < 1024; u += 256) {
            int row = u >> 3, cc = (u & 7) * 4;
            float4 v = *(const float4*)(Wa + (m0 + row) * 512 + k0 + cc);
            __nv_bfloat162* d2 = (__nv_bfloat162*)(As + row * 40 + cc);
            d2[0] = __floats2bfloat162_rn(v.x, v.y);
            d2[1] = __floats2bfloat162_rn(v.z, v.w);
        }
#pragma unroll
        for (int i = 0; i < 4; i++) {
            int o = k0 + r8 + i * 8;
            float4 v = *(const float4*)(w_qkv + (size_t)o * D_SZ + n0 + c4 * 4);
            __nv_bfloat162* d2 = (__nv_bfloat162*)(Bs + (r8 + i * 8) * 136 + c4 * 4);
            d2[0] = __floats2bfloat162_rn(v.x, v.y);
            d2[1] = __floats2bfloat162_rn(v.z, v.w);
        }
        __syncthreads();
#pragma unroll
        for (int kt = 0; kt < 2; kt++) {
            uint32_t a[4][4];
            int lrow = lane & 15, lcol = kt * 16 + (lane >> 4) * 8;
#pragma unroll
            for (int i = 0; i < 4; i++)
                ldsm_x4(a[i][0], a[i][1], a[i][2], a[i][3],
                        smem_u32(As + (wm * 64 + i * 16 + lrow) * 40 + lcol));
            uint32_t bb[4][2];
            int l = lane & 15;
#pragma unroll
            for (int j = 0; j < 4; j++)
                ldsm_x2_t(bb[j][0], bb[j][1],
                          smem_u32(Bs + (kt * 16 + l) * 136 + wn * 32 + j * 8));
#pragma unroll
            for (int i = 0; i < 4; i++)
#pragma unroll
                for (int j = 0; j < 4; j++)
                    mma16816(acc[i][j], a[i][0], a[i][1], a[i][2], a[i][3], bb[j][0], bb[j][1]);
        }
    }
#pragma unroll
    for (int i = 0; i < 4; i++)
#pragma unroll
        for (int j = 0; j < 4; j++) {
            int row = m0 + wm * 64 + i * 16 + (lane >> 2);
            int col = n0 + wn * 32 + j * 8 + (lane & 3) * 2;
            if (row < 384 && col < 384) {
                __nv_bfloat162 v01 = __floats2bfloat162_rn(Q_SCALE * acc[i][j][0], Q_SCALE * acc[i][j][1]);
                __nv_bfloat162 v23 = __floats2bfloat162_rn(Q_SCALE * acc[i][j][2], Q_SCALE * acc[i][j][3]);
                *(__nv_bfloat162*)(g_W3 + ((size_t)b * 384 + row) * 384 + col)       = v01;
                *(__nv_bfloat162*)(g_W3 + ((size_t)b * 384 + row + 8) * 384 + col)   = v23;
            }
        }
}

// ---------------- kernel 8: final = W3[b] @ xn + b_out + x, B-panel resident -
__global__ __launch_bounds__(256) void k_final(const float* __restrict__ x,
                                               const float* __restrict__ b_out,
                                               float* __restrict__ out) {
    extern __shared__ __align__(16) char dyn[];
    __nv_bfloat16* Bp = (__nv_bfloat16*)dyn;                                  // 384 x 136
    __nv_bfloat16* As = (__nv_bfloat16*)(dyn + D_SZ * BP_STRIDE * 2);         // 2 x 128 x 40
    const int t  = threadIdx.x;
    const int b  = blockIdx.y;
    const int n0 = blockIdx.x * 128;
    const int wid = t >> 5, lane = t & 31;
    const int wm = wid >> 2, wn = wid & 3;
    const __nv_bfloat16* Ag = g_W3 + (size_t)b * 384 * 384;
    const __nv_bfloat16* Bg = g_xn + (size_t)b * D_SZ * N_SZ;

#pragma unroll
    for (int u = t; u < D_SZ * 16; u += 256) {
        int row = u >> 4, c8 = (u & 15) * 8;
        *(uint4*)(Bp + row * BP_STRIDE + c8) = *(const uint4*)(Bg + (size_t)row * N_SZ + n0 + c8);
    }

    const int ar0 = t >> 2,         ac0 = (t & 3) * 8;
    const int ar1 = (t + 256) >> 2, ac1 = ((t + 256) & 3) * 8;
    const int KSTEPS = D_SZ / 32;   // 12

    for (int mt = 0; mt < 3; mt++) {
        const int m0 = mt * 128;
        uint4 a0 = *(const uint4*)(Ag + (m0 + ar0) * D_SZ + ac0);
        uint4 a1 = *(const uint4*)(Ag + (m0 + ar1) * D_SZ + ac1);
        __syncthreads();
        *(uint4*)(As + ar0 * AS_STRIDE + ac0) = a0;
        *(uint4*)(As + ar1 * AS_STRIDE + ac1) = a1;
        __syncthreads();

        float acc[4][4][4];
#pragma unroll
        for (int i = 0; i < 4; i++)
#pragma unroll
            for (int j = 0; j < 4; j++)
#pragma unroll
                for (int r = 0; r < 4; r++) acc[i][j][r] = 0.f;

        int s = 0;
        for (int k = 0; k < KSTEPS; k++) {
            if (k + 1 < KSTEPS) {
                int kn = (k + 1) * 32;
                a0 = *(const uint4*)(Ag + (m0 + ar0) * D_SZ + kn + ac0);
                a1 = *(const uint4*)(Ag + (m0 + ar1) * D_SZ + kn + ac1);
            }
            const __nv_bfloat16* Ab = As + s * (128 * AS_STRIDE);
            const __nv_bfloat16* Bb = Bp + (k * 32) * BP_STRIDE;
#pragma unroll
            for (int kt = 0; kt < 2; kt++) {
                uint32_t a[4][4];
                int lrow = lane & 15, lcol = kt * 16 + (lane >> 4) * 8;
#pragma unroll
                for (int i = 0; i < 4; i++)
                    ldsm_x4(a[i][0], a[i][1], a[i][2], a[i][3],
                            smem_u32(Ab + (wm * 64 + i * 16 + lrow) * AS_STRIDE + lcol));
                uint32_t bb[4][2];
                int l = lane & 15;
#pragma unroll
                for (int j = 0; j < 4; j++)
                    ldsm_x2_t(bb[j][0], bb[j][1],
                              smem_u32(Bb + (kt * 16 + l) * BP_STRIDE + wn * 32 + j * 8));
#pragma unroll
                for (int i = 0; i < 4; i++)
#pragma unroll
                    for (int j = 0; j < 4; j++)
                        mma16816(acc[i][j], a[i][0], a[i][1], a[i][2], a[i][3], bb[j][0], bb[j][1]);
            }
            if (k + 1 < KSTEPS) {
                int ns = s ^ 1;
                __nv_bfloat16* An = As + ns * (128 * AS_STRIDE);
                *(uint4*)(An + ar0 * AS_STRIDE + ac0) = a0;
                *(uint4*)(An + ar1 * AS_STRIDE + ac1) = a1;
                __syncthreads();
                s = ns;
            }
        }
#pragma unroll
        for (int i = 0; i < 4; i++)
#pragma unroll
            for (int j = 0; j < 4; j++) {
                int row = m0 + wm * 64 + i * 16 + (lane >> 2);
                int col = n0 + wn * 32 + j * 8 + (lane & 3) * 2;
                float bo0 = b_out[row];
                float bo1 = b_out[row + 8];
                float2 xr0 = *(const float2*)(x + ((size_t)b * D_SZ + row) * N_SZ + col);
                float2 xr1 = *(const float2*)(x + ((size_t)b * D_SZ + row + 8) * N_SZ + col);
                *(float2*)(out + ((size_t)b * D_SZ + row) * N_SZ + col) =
                    make_float2(acc[i][j][0] + bo0 + xr0.x, acc[i][j][1] + bo0 + xr0.y);
                *(float2*)(out + ((size_t)b * D_SZ + row + 8) * N_SZ + col) =
                    make_float2(acc[i][j][2] + bo1 + xr1.x, acc[i][j][3] + bo1 + xr1.y);
            }
    }
}

// ---------------- launch ----------------------------------------------------
extern "C" void kernel_launch(void* const* d_in, const int* in_sizes, int n_in,
                              void* d_out, int out_size) {
    (void)in_sizes; (void)n_in; (void)out_size;
    const float* x     = (const float*)d_in[0];
    const float* gamma = (const float*)d_in[1];
    const float* beta  = (const float*)d_in[2];
    const float* w_qkv = (const float*)d_in[3];
    const float* w_out = (const float*)d_in[4];
    const float* b_out = (const float*)d_in[5];
    float* out = (float*)d_out;

    const int panel_smem = (D_SZ * BP_STRIDE + 2 * 128 * AS_STRIDE) * (int)sizeof(__nv_bfloat16);
    const int ln_smem = D_SZ * 33 * (int)sizeof(float);
    cudaFuncSetAttribute(k_lnxn,    cudaFuncAttributeMaxDynamicSharedMemorySize, ln_smem);
    cudaFuncSetAttribute(k_gemm_kv, cudaFuncAttributeMaxDynamicSharedMemorySize, panel_smem);
    cudaFuncSetAttribute(k_final,   cudaFuncAttributeMaxDynamicSharedMemorySize, panel_smem);

    k_prep<<<(KV_M * D_SZ + 255) / 256, 256>>>(w_qkv);
    k_lnxn<<<dim3(N_SZ / 32, B_SZ), 256, ln_smem>>>(x, gamma, beta);
    k_gemm_kv<<<dim3(NTILES, B_SZ), 256, panel_smem>>>();
    k_combine<<<B_SZ * 512 / 8, 256>>>();
    k_ctx<<<dim3(8, HEADS, B_SZ), 256>>>();
    k_ctx_reduce<<<(B_SZ * HEADS * 64 * 64 + 255) / 256, 256>>>();
    k_w2<<<dim3(384 * 512 / 256, B_SZ), 256>>>(w_out);
    k_w3<<<dim3(3, 3, B_SZ), 256>>>(w_qkv);
    k_final<<<dim3(N_SZ / 128, B_SZ), 256, panel_smem>>>(x, b_out, out);
}

// round 12
// speedup vs baseline: 1.0574x; 1.0574x over previous
#include <cuda_runtime.h>
#include <cuda_bf16.h>
#include <cstdint>

#define B_SZ  16
#define D_SZ  384
#define N_SZ  8192
#define KV_M  1024      // k rows 0..511, v rows 512..1023
#define HEADS 8
#define LN_EPS 1e-5f
#define Q_SCALE 0.125f  // 64^-0.5
#define AS_STRIDE 40    // padded bf16 stride for 32-col A tile (80B = 5x16B)
#define BS_STRIDE 136   // padded bf16 stride for 128-col B tile (272B = 17x16B)
#define CS_STRIDE 72    // padded bf16 stride for 64-col ctx tiles (144B = 9x16B)
#define NTILES (N_SZ / 128)   // 64

// ---------------- scratch (static device globals: allocation-free) ----------
__device__ __nv_bfloat16 g_xn[(size_t)B_SZ * D_SZ * N_SZ];     // 100 MB normalized x (bf16)
__device__ __nv_bfloat16 g_kv[(size_t)B_SZ * KV_M * N_SZ];     // 268 MB raw K,V
__device__ __nv_bfloat16 g_wkv[KV_M * D_SZ];                    // bf16 copy of w_qkv rows 512..1535
__device__ float         g_pmx[(size_t)B_SZ * 512 * NTILES];    // per-(row,ntile) max partials
__device__ float         g_pse[(size_t)B_SZ * 512 * NTILES];    // per-(row,ntile) sum-exp partials
__device__ float         g_rowmx[B_SZ * 512];
__device__ float         g_rowinv[B_SZ * 512];
__device__ float         g_ctx_part[8][B_SZ * HEADS * 64 * 64]; // split-K partials (16 MB)
__device__ float         g_ctx[B_SZ * HEADS * 64 * 64];
__device__ float         g_W2[(size_t)B_SZ * 384 * 512];
__device__ __nv_bfloat16 g_W3[(size_t)B_SZ * 384 * 384];

// ---------------- mma / ldmatrix helpers ------------------------------------
__device__ __forceinline__ uint32_t smem_u32(const void* p) {
    return (uint32_t)__cvta_generic_to_shared(p);
}
__device__ __forceinline__ void ldsm_x4(uint32_t& r0, uint32_t& r1, uint32_t& r2, uint32_t& r3, uint32_t a) {
    asm volatile("ldmatrix.sync.aligned.m8n8.x4.shared.b16 {%0,%1,%2,%3},[%4];\n"
                 : "=r"(r0), "=r"(r1), "=r"(r2), "=r"(r3) : "r"(a));
}
__device__ __forceinline__ void ldsm_x2(uint32_t& r0, uint32_t& r1, uint32_t a) {
    asm volatile("ldmatrix.sync.aligned.m8n8.x2.shared.b16 {%0,%1},[%2];\n"
                 : "=r"(r0), "=r"(r1) : "r"(a));
}
__device__ __forceinline__ void ldsm_x2_t(uint32_t& r0, uint32_t& r1, uint32_t a) {
    asm volatile("ldmatrix.sync.aligned.m8n8.x2.trans.shared.b16 {%0,%1},[%2];\n"
                 : "=r"(r0), "=r"(r1) : "r"(a));
}
__device__ __forceinline__ void mma16816(float c[4], uint32_t a0, uint32_t a1, uint32_t a2, uint32_t a3,
                                         uint32_t b0, uint32_t b1) {
    asm volatile("mma.sync.aligned.m16n8k16.row.col.f32.bf16.bf16.f32 "
                 "{%0,%1,%2,%3},{%4,%5,%6,%7},{%8,%9},{%0,%1,%2,%3};\n"
                 : "+f"(c[0]), "+f"(c[1]), "+f"(c[2]), "+f"(c[3])
                 : "r"(a0), "r"(a1), "r"(a2), "r"(a3), "r"(b0), "r"(b1));
}
// exp((k - mx)) * inv applied to 8 bf16 values packed in a uint4
__device__ __forceinline__ uint4 expk4(uint4 raw, float mx, float inv) {
    __nv_bfloat162* h2 = (__nv_bfloat162*)&raw;
    uint4 outp;
    __nv_bfloat162* o2 = (__nv_bfloat162*)&outp;
#pragma unroll
    for (int j = 0; j < 4; j++) {
        float2 f = __bfloat1622float2(h2[j]);
        o2[j] = __floats2bfloat162_rn(__expf(f.x - mx) * inv, __expf(f.y - mx) * inv);
    }
    return outp;
}

// ---------------- kernel 1: convert KV weights to bf16 ----------------------
__global__ __launch_bounds__(256) void k_prep(const float* __restrict__ w_qkv) {
    int i = blockIdx.x * 256 + threadIdx.x;
    if (i < KV_M * D_SZ) g_wkv[i] = __float2bfloat16(w_qkv[512 * D_SZ + i]);
}

// ---------------- kernel 2: single-pass layernorm via smem tile --------------
__global__ __launch_bounds__(256) void k_lnxn(const float* __restrict__ x,
                                              const float* __restrict__ gamma,
                                              const float* __restrict__ beta) {
    extern __shared__ __align__(16) float tile[];      // 384*33 floats
    __shared__ float sred[8][32], qred[8][32];
    __shared__ float mcol[32], rcol[32];
    const int t = threadIdx.x;
    const int n0 = blockIdx.x * 32;
    const int b = blockIdx.y;
    const int col = t & 31, sub = t >> 5;
    const float* xp = x + (size_t)b * D_SZ * N_SZ + n0;

    for (int row = sub; row < D_SZ; row += 8)
        tile[row * 33 + col] = xp[(size_t)row * N_SZ + col];
    __syncthreads();

    float s = 0.f, q = 0.f;
    for (int row = sub; row < D_SZ; row += 8) {
        float v = tile[row * 33 + col];
        s += v; q += v * v;
    }
    sred[sub][col] = s; qred[sub][col] = q;
    __syncthreads();
    if (t < 32) {
        float ss = 0.f, qq = 0.f;
#pragma unroll
        for (int i = 0; i < 8; i++) { ss += sred[i][t]; qq += qred[i][t]; }
        const float inv_d = 1.f / D_SZ;
        float m = ss * inv_d;
        mcol[t] = m;
        rcol[t] = rsqrtf(qq * inv_d - m * m + LN_EPS);
    }
    __syncthreads();

    const float m = mcol[col], r = rcol[col];
    __nv_bfloat16* op = g_xn + (size_t)b * D_SZ * N_SZ + n0;
    for (int row = sub; row < D_SZ; row += 8) {
        float gd = gamma[row], bd = beta[row];
        op[(size_t)row * N_SZ + col] = __float2bfloat16((tile[row * 33 + col] - m) * r * gd + bd);
    }
}

// ---------------- kernel 3: KV GEMM, tiled + double-buffered, fused K stats --
// grid (ntile, mtile, b); C[1024 x 8192] = Wkv[1024 x 384] @ xn[384 x 8192]
__global__ __launch_bounds__(256) void k_gemm_kv() {
    __shared__ __align__(16) __nv_bfloat16 As[2][128 * AS_STRIDE];
    __shared__ __align__(16) __nv_bfloat16 Bs[2][32 * BS_STRIDE];
    __shared__ float smax[128 * 4];
    __shared__ float ssum[128 * 4];
    const int t  = threadIdx.x;
    const int b  = blockIdx.z;
    const int m0 = blockIdx.y * 128;
    const int ntile = blockIdx.x;
    const int n0 = ntile * 128;
    const int wid = t >> 5, lane = t & 31;
    const int wm = wid >> 2, wn = wid & 3;

    float acc[4][4][4];
#pragma unroll
    for (int i = 0; i < 4; i++)
#pragma unroll
        for (int j = 0; j < 4; j++)
#pragma unroll
            for (int r = 0; r < 4; r++) acc[i][j][r] = 0.f;

    const int ar0 = t >> 2,         ac0 = (t & 3) * 8;
    const int ar1 = (t + 256) >> 2, ac1 = ((t + 256) & 3) * 8;
    const int br = t >> 3, bc = (t & 7) * 8;

    const __nv_bfloat16* Ag = g_wkv;
    const __nv_bfloat16* Bg = g_xn + (size_t)b * D_SZ * N_SZ;

    uint4 a0, a1, b0, b1;
    a0 = *(const uint4*)(Ag + (m0 + ar0) * D_SZ + ac0);
    a1 = *(const uint4*)(Ag + (m0 + ar1) * D_SZ + ac1);
    b0 = *(const uint4*)(Bg + (size_t)br * N_SZ + n0 + bc);
    b1 = *(const uint4*)(Bg + (size_t)br * N_SZ + n0 + bc + 64);
    *(uint4*)(As[0] + ar0 * AS_STRIDE + ac0) = a0;
    *(uint4*)(As[0] + ar1 * AS_STRIDE + ac1) = a1;
    *(uint4*)(Bs[0] + br * BS_STRIDE + bc)      = b0;
    *(uint4*)(Bs[0] + br * BS_STRIDE + bc + 64) = b1;
    __syncthreads();

    const int KSTEPS = D_SZ / 32;   // 12
    int s = 0;
    for (int k = 0; k < KSTEPS; k++) {
        if (k + 1 < KSTEPS) {
            int kn = (k + 1) * 32;
            a0 = *(const uint4*)(Ag + (m0 + ar0) * D_SZ + kn + ac0);
            a1 = *(const uint4*)(Ag + (m0 + ar1) * D_SZ + kn + ac1);
            b0 = *(const uint4*)(Bg + (size_t)(kn + br) * N_SZ + n0 + bc);
            b1 = *(const uint4*)(Bg + (size_t)(kn + br) * N_SZ + n0 + bc + 64);
        }
#pragma unroll
        for (int kt = 0; kt < 2; kt++) {
            uint32_t a[4][4];
            int lrow = lane & 15, lcol = kt * 16 + (lane >> 4) * 8;
#pragma unroll
            for (int i = 0; i < 4; i++)
                ldsm_x4(a[i][0], a[i][1], a[i][2], a[i][3],
                        smem_u32(As[s] + (wm * 64 + i * 16 + lrow) * AS_STRIDE + lcol));
            uint32_t bb[4][2];
            int l = lane & 15;
#pragma unroll
            for (int j = 0; j < 4; j++)
                ldsm_x2_t(bb[j][0], bb[j][1],
                          smem_u32(Bs[s] + (kt * 16 + l) * BS_STRIDE + wn * 32 + j * 8));
#pragma unroll
            for (int i = 0; i < 4; i++)
#pragma unroll
                for (int j = 0; j < 4; j++)
                    mma16816(acc[i][j], a[i][0], a[i][1], a[i][2], a[i][3], bb[j][0], bb[j][1]);
        }
        if (k + 1 < KSTEPS) {
            int ns = s ^ 1;
            *(uint4*)(As[ns] + ar0 * AS_STRIDE + ac0) = a0;
            *(uint4*)(As[ns] + ar1 * AS_STRIDE + ac1) = a1;
            *(uint4*)(Bs[ns] + br * BS_STRIDE + bc)      = b0;
            *(uint4*)(Bs[ns] + br * BS_STRIDE + bc + 64) = b1;
            __syncthreads();
            s = ns;
        }
    }
    // store C tile (bf16)
#pragma unroll
    for (int i = 0; i < 4; i++)
#pragma unroll
        for (int j = 0; j < 4; j++) {
            int row = m0 + wm * 64 + i * 16 + (lane >> 2);
            int col = n0 + wn * 32 + j * 8 + (lane & 3) * 2;
            __nv_bfloat162 v01 = __floats2bfloat162_rn(acc[i][j][0], acc[i][j][1]);
            __nv_bfloat162 v23 = __floats2bfloat162_rn(acc[i][j][2], acc[i][j][3]);
            *(__nv_bfloat162*)(g_kv + ((size_t)b * KV_M + row) * N_SZ + col)     = v01;
            *(__nv_bfloat162*)(g_kv + ((size_t)b * KV_M + row + 8) * N_SZ + col) = v23;
        }

    // fused softmax partial stats for K rows (fp32 accs, this CTA's 128 cols)
    if (m0 < 512) {
#pragma unroll
        for (int i = 0; i < 4; i++) {
            float mv0 = -3.0e38f, mv1 = -3.0e38f;
#pragma unroll
            for (int j = 0; j < 4; j++) {
                mv0 = fmaxf(mv0, fmaxf(acc[i][j][0], acc[i][j][1]));
                mv1 = fmaxf(mv1, fmaxf(acc[i][j][2], acc[i][j][3]));
            }
#pragma unroll
            for (int o = 1; o <= 2; o <<= 1) {
                mv0 = fmaxf(mv0, __shfl_xor_sync(0xffffffffu, mv0, o));
                mv1 = fmaxf(mv1, __shfl_xor_sync(0xffffffffu, mv1, o));
            }
            if ((lane & 3) == 0) {
                int r0 = wm * 64 + i * 16 + (lane >> 2);
                smax[r0 * 4 + wn]       = mv0;
                smax[(r0 + 8) * 4 + wn] = mv1;
            }
        }
        __syncthreads();
#pragma unroll
        for (int i = 0; i < 4; i++) {
            int r0 = wm * 64 + i * 16 + (lane >> 2);
            float rm0 = fmaxf(fmaxf(smax[r0 * 4 + 0], smax[r0 * 4 + 1]),
                              fmaxf(smax[r0 * 4 + 2], smax[r0 * 4 + 3]));
            float rm1 = fmaxf(fmaxf(smax[(r0 + 8) * 4 + 0], smax[(r0 + 8) * 4 + 1]),
                              fmaxf(smax[(r0 + 8) * 4 + 2], smax[(r0 + 8) * 4 + 3]));
            float s0 = 0.f, s1 = 0.f;
#pragma unroll
            for (int j = 0; j < 4; j++) {
                s0 += __expf(acc[i][j][0] - rm0) + __expf(acc[i][j][1] - rm0);
                s1 += __expf(acc[i][j][2] - rm1) + __expf(acc[i][j][3] - rm1);
            }
#pragma unroll
            for (int o = 1; o <= 2; o <<= 1) {
                s0 += __shfl_xor_sync(0xffffffffu, s0, o);
                s1 += __shfl_xor_sync(0xffffffffu, s1, o);
            }
            if ((lane & 3) == 0) {
                ssum[r0 * 4 + wn]       = s0;
                ssum[(r0 + 8) * 4 + wn] = s1;
            }
        }
        __syncthreads();
        if (t < 128) {
            float rm = fmaxf(fmaxf(smax[t * 4 + 0], smax[t * 4 + 1]),
                             fmaxf(smax[t * 4 + 2], smax[t * 4 + 3]));
            float sv = ssum[t * 4 + 0] + ssum[t * 4 + 1] + ssum[t * 4 + 2] + ssum[t * 4 + 3];
            size_t idx = ((size_t)(b * 512 + m0 + t)) * NTILES + ntile;
            g_pmx[idx] = rm;
            g_pse[idx] = sv;
        }
    }
}

// ---------------- kernel 4: combine per-ntile stats -> rowmx, rowinv --------
__global__ __launch_bounds__(256) void k_combine() {
    const int w = (blockIdx.x * 256 + threadIdx.x) >> 5;   // global row 0..8191
    const int lane = threadIdx.x & 31;
    const float* pm = g_pmx + (size_t)w * NTILES;
    const float* ps = g_pse + (size_t)w * NTILES;
    float m0 = pm[lane], m1 = pm[lane + 32];
    float m = fmaxf(m0, m1);
#pragma unroll
    for (int o = 16; o > 0; o >>= 1) m = fmaxf(m, __shfl_xor_sync(0xffffffffu, m, o));
    float s = ps[lane] * __expf(m0 - m) + ps[lane + 32] * __expf(m1 - m);
#pragma unroll
    for (int o = 16; o > 0; o >>= 1) s += __shfl_xor_sync(0xffffffffu, s, o);
    if (lane == 0) {
        g_rowmx[w]  = m;
        g_rowinv[w] = 1.f / s;
    }
}

// ---------------- kernel 5: context = softmax(K) @ V^T -----------------------
// 256 threads, 64-col double-buffered steps, register prefetch, exp fused.
__global__ __launch_bounds__(256) void k_ctx() {
    __shared__ __align__(16) __nv_bfloat16 Ks[2][64 * CS_STRIDE];
    __shared__ __align__(16) __nv_bfloat16 Vs[2][64 * CS_STRIDE];
    __shared__ float s_mx[64], s_inv[64];
    const int t = threadIdx.x;
    const int split = blockIdx.x, h = blockIdx.y, b = blockIdx.z;
    const __nv_bfloat16* kp = g_kv + ((size_t)(b * KV_M + h * 64)) * N_SZ;
    const __nv_bfloat16* vp = g_kv + ((size_t)(b * KV_M + 512 + h * 64)) * N_SZ;
    const int wid = t >> 5, lane = t & 31;
    const int wm = wid >> 2, wn = wid & 3;      // 2 x 4 warp grid over 64x64

    if (t < 64) {
        s_mx[t]  = g_rowmx[b * 512 + h * 64 + t];
        s_inv[t] = g_rowinv[b * 512 + h * 64 + t];
    }
    __syncthreads();

    // per-thread load slots: 64 rows x 8 chunks (8 bf16 each) = 512 chunks; 2/thread
    const int r0 = t >> 3,         c0 = (t & 7) * 8;
    const int r1 = (t + 256) >> 3, c1 = ((t + 256) & 7) * 8;
    const float mx0 = s_mx[r0], iv0 = s_inv[r0];
    const float mx1 = s_mx[r1], iv1 = s_inv[r1];

    float acc[2][2][4];
#pragma unroll
    for (int i = 0; i < 2; i++)
#pragma unroll
        for (int j = 0; j < 2; j++)
#pragma unroll
            for (int r = 0; r < 4; r++) acc[i][j][r] = 0.f;

    const int col_base = split * 1024;
    const int STEPS = 16;          // 1024 cols / 64

    // prologue: load step 0
    uint4 ka = *(const uint4*)(kp + (size_t)r0 * N_SZ + col_base + c0);
    uint4 kb = *(const uint4*)(kp + (size_t)r1 * N_SZ + col_base + c1);
    uint4 va = *(const uint4*)(vp + (size_t)r0 * N_SZ + col_base + c0);
    uint4 vb = *(const uint4*)(vp + (size_t)r1 * N_SZ + col_base + c1);
    *(uint4*)(Ks[0] + r0 * CS_STRIDE + c0) = expk4(ka, mx0, iv0);
    *(uint4*)(Ks[0] + r1 * CS_STRIDE + c1) = expk4(kb, mx1, iv1);
    *(uint4*)(Vs[0] + r0 * CS_STRIDE + c0) = va;
    *(uint4*)(Vs[0] + r1 * CS_STRIDE + c1) = vb;
    __syncthreads();

    int s = 0;
    for (int step = 0; step < STEPS; step++) {
        if (step + 1 < STEPS) {
            int kk = col_base + (step + 1) * 64;
            ka = *(const uint4*)(kp + (size_t)r0 * N_SZ + kk + c0);
            kb = *(const uint4*)(kp + (size_t)r1 * N_SZ + kk + c1);
            va = *(const uint4*)(vp + (size_t)r0 * N_SZ + kk + c0);
            vb = *(const uint4*)(vp + (size_t)r1 * N_SZ + kk + c1);
        }
#pragma unroll
        for (int kc = 0; kc < 4; kc++) {        // 4 x k=16 chunks
            uint32_t a[2][4];
            int lrow = lane & 15, lcol = kc * 16 + (lane >> 4) * 8;
#pragma unroll
            for (int i = 0; i < 2; i++)
                ldsm_x4(a[i][0], a[i][1], a[i][2], a[i][3],
                        smem_u32(Ks[s] + (wm * 32 + i * 16 + lrow) * CS_STRIDE + lcol));
            uint32_t bb[2][2];
            int l = lane & 15;
#pragma unroll
            for (int j = 0; j < 2; j++) {
                int e  = wn * 16 + j * 8 + (l & 7);
                int kcc = kc * 16 + (l >> 3) * 8;
                ldsm_x2(bb[j][0], bb[j][1], smem_u32(Vs[s] + e * CS_STRIDE + kcc));
            }
#pragma unroll
            for (int i = 0; i < 2; i++)
#pragma unroll
                for (int j = 0; j < 2; j++)
                    mma16816(acc[i][j], a[i][0], a[i][1], a[i][2], a[i][3], bb[j][0], bb[j][1]);
        }
        if (step + 1 < STEPS) {
            int ns = s ^ 1;
            *(uint4*)(Ks[ns] + r0 * CS_STRIDE + c0) = expk4(ka, mx0, iv0);
            *(uint4*)(Ks[ns] + r1 * CS_STRIDE + c1) = expk4(kb, mx1, iv1);
            *(uint4*)(Vs[ns] + r0 * CS_STRIDE + c0) = va;
            *(uint4*)(Vs[ns] + r1 * CS_STRIDE + c1) = vb;
            __syncthreads();
            s = ns;
        }
    }
    float* dst = g_ctx_part[split] + ((b * HEADS + h) * 64) * 64;
#pragma unroll
    for (int i = 0; i < 2; i++)
#pragma unroll
        for (int j = 0; j < 2; j++) {
            int row = wm * 32 + i * 16 + (lane >> 2);
            int col = wn * 16 + j * 8 + (lane & 3) * 2;
            *(float2*)(dst + row * 64 + col)       = make_float2(acc[i][j][0], acc[i][j][1]);
            *(float2*)(dst + (row + 8) * 64 + col) = make_float2(acc[i][j][2], acc[i][j][3]);
        }
}

__global__ __launch_bounds__(256) void k_ctx_reduce() {
    int i = blockIdx.x * 256 + threadIdx.x;
    if (i < B_SZ * HEADS * 64 * 64) {
        float s = 0.f;
#pragma unroll
        for (int p = 0; p < 8; p++) s += g_ctx_part[p][i];
        g_ctx[i] = s;
    }
}

// ---------------- kernel 6: W2[b][dp][h*64+d] = sum_e w_out[dp][h*64+e]*ctx[b,h,d,e]
__global__ __launch_bounds__(256) void k_w2(const float* __restrict__ w_out) {
    int idx = blockIdx.x * 256 + threadIdx.x;   // 0..196607
    int b = blockIdx.y;
    int dp = idx >> 9;
    int o  = idx & 511;
    int h = o >> 6, d = o & 63;
    const float* wrow = w_out + dp * 512 + h * 64;
    const float* crow = g_ctx + ((b * HEADS + h) * 64 + d) * 64;
    float s = 0.f;
#pragma unroll
    for (int e = 0; e < 64; e++) s += wrow[e] * crow[e];
    g_W2[((size_t)b * 384 + dp) * 512 + o] = s;
}

// ---------------- kernel 7: W3[b] = SCALE * W2[b] @ Wq   (384x384, K=512) ---
__global__ __launch_bounds__(256) void k_w3(const float* __restrict__ w_qkv) {
    __shared__ __align__(16) __nv_bfloat16 As[128 * AS_STRIDE];
    __shared__ __align__(16) __nv_bfloat16 Bs[32 * BS_STRIDE];
    const int t  = threadIdx.x;
    const int b  = blockIdx.z;
    const int m0 = blockIdx.y * 128;
    const int n0 = blockIdx.x * 128;
    const int wid = t >> 5, lane = t & 31;
    const int wm = wid >> 2, wn = wid & 3;
    const float* Wa = g_W2 + (size_t)b * 384 * 512;

    float acc[4][4][4];
#pragma unroll
    for (int i = 0; i < 4; i++)
#pragma unroll
        for (int j = 0; j < 4; j++)
#pragma unroll
            for (int r = 0; r < 4; r++) acc[i][j][r] = 0.f;

    const int r8 = t >> 5;
    const int c4 = t & 31;

    for (int k0 = 0; k0 < 512; k0 += 32) {
        __syncthreads();
#pragma unroll
        for (int u = t; u < 1024; u += 256) {
            int row = u >> 3, cc = (u & 7) * 4;
            float4 v = *(const float4*)(Wa + (m0 + row) * 512 + k0 + cc);
            __nv_bfloat162* d2 = (__nv_bfloat162*)(As + row * AS_STRIDE + cc);
            d2[0] = __floats2bfloat162_rn(v.x, v.y);
            d2[1] = __floats2bfloat162_rn(v.z, v.w);
        }
#pragma unroll
        for (int i = 0; i < 4; i++) {
            int o = k0 + r8 + i * 8;
            float4 v = *(const float4*)(w_qkv + (size_t)o * D_SZ + n0 + c4 * 4);
            __nv_bfloat162* d2 = (__nv_bfloat162*)(Bs + (r8 + i * 8) * BS_STRIDE + c4 * 4);
            d2[0] = __floats2bfloat162_rn(v.x, v.y);
            d2[1] = __floats2bfloat162_rn(v.z, v.w);
        }
        __syncthreads();
#pragma unroll
        for (int kt = 0; kt < 2; kt++) {
            uint32_t a[4][4];
            int lrow = lane & 15, lcol = kt * 16 + (lane >> 4) * 8;
#pragma unroll
            for (int i = 0; i < 4; i++)
                ldsm_x4(a[i][0], a[i][1], a[i][2], a[i][3],
                        smem_u32(As + (wm * 64 + i * 16 + lrow) * AS_STRIDE + lcol));
            uint32_t bb[4][2];
            int l = lane & 15;
#pragma unroll
            for (int j = 0; j < 4; j++)
                ldsm_x2_t(bb[j][0], bb[j][1],
                          smem_u32(Bs + (kt * 16 + l) * BS_STRIDE + wn * 32 + j * 8));
#pragma unroll
            for (int i = 0; i < 4; i++)
#pragma unroll
                for (int j = 0; j < 4; j++)
                    mma16816(acc[i][j], a[i][0], a[i][1], a[i][2], a[i][3], bb[j][0], bb[j][1]);
        }
    }
#pragma unroll
    for (int i = 0; i < 4; i++)
#pragma unroll
        for (int j = 0; j < 4; j++) {
            int row = m0 + wm * 64 + i * 16 + (lane >> 2);
            int col = n0 + wn * 32 + j * 8 + (lane & 3) * 2;
            if (row < 384 && col < 384) {
                __nv_bfloat162 v01 = __floats2bfloat162_rn(Q_SCALE * acc[i][j][0], Q_SCALE * acc[i][j][1]);
                __nv_bfloat162 v23 = __floats2bfloat162_rn(Q_SCALE * acc[i][j][2], Q_SCALE * acc[i][j][3]);
                *(__nv_bfloat162*)(g_W3 + ((size_t)b * 384 + row) * 384 + col)       = v01;
                *(__nv_bfloat162*)(g_W3 + ((size_t)b * 384 + row + 8) * 384 + col)   = v23;
            }
        }
}

// ---------------- kernel 8: final = W3[b] @ xn + b_out + x, tiled + dbuf -----
__global__ __launch_bounds__(256) void k_final(const float* __restrict__ x,
                                               const float* __restrict__ b_out,
                                               float* __restrict__ out) {
    __shared__ __align__(16) __nv_bfloat16 As[2][128 * AS_STRIDE];
    __shared__ __align__(16) __nv_bfloat16 Bs[2][32 * BS_STRIDE];
    const int t  = threadIdx.x;
    const int b  = blockIdx.z;
    const int m0 = blockIdx.y * 128;
    const int n0 = blockIdx.x * 128;
    const int wid = t >> 5, lane = t & 31;
    const int wm = wid >> 2, wn = wid & 3;
    const __nv_bfloat16* Ag = g_W3 + (size_t)b * 384 * 384;
    const __nv_bfloat16* Bg = g_xn + (size_t)b * D_SZ * N_SZ;

    float acc[4][4][4];
#pragma unroll
    for (int i = 0; i < 4; i++)
#pragma unroll
        for (int j = 0; j < 4; j++)
#pragma unroll
            for (int r = 0; r < 4; r++) acc[i][j][r] = 0.f;

    const int ar0 = t >> 2,         ac0 = (t & 3) * 8;
    const int ar1 = (t + 256) >> 2, ac1 = ((t + 256) & 3) * 8;
    const int br = t >> 3, bc = (t & 7) * 8;

    uint4 a0, a1, b0, b1;
    a0 = *(const uint4*)(Ag + (m0 + ar0) * D_SZ + ac0);
    a1 = *(const uint4*)(Ag + (m0 + ar1) * D_SZ + ac1);
    b0 = *(const uint4*)(Bg + (size_t)br * N_SZ + n0 + bc);
    b1 = *(const uint4*)(Bg + (size_t)br * N_SZ + n0 + bc + 64);
    *(uint4*)(As[0] + ar0 * AS_STRIDE + ac0) = a0;
    *(uint4*)(As[0] + ar1 * AS_STRIDE + ac1) = a1;
    *(uint4*)(Bs[0] + br * BS_STRIDE + bc)      = b0;
    *(uint4*)(Bs[0] + br * BS_STRIDE + bc + 64) = b1;
    __syncthreads();

    const int KSTEPS = D_SZ / 32;   // 12
    int s = 0;
    for (int k = 0; k < KSTEPS; k++) {
        if (k + 1 < KSTEPS) {
            int kn = (k + 1) * 32;
            a0 = *(const uint4*)(Ag + (m0 + ar0) * D_SZ + kn + ac0);
            a1 = *(const uint4*)(Ag + (m0 + ar1) * D_SZ + kn + ac1);
            b0 = *(const uint4*)(Bg + (size_t)(kn + br) * N_SZ + n0 + bc);
            b1 = *(const uint4*)(Bg + (size_t)(kn + br) * N_SZ + n0 + bc + 64);
        }
#pragma unroll
        for (int kt = 0; kt < 2; kt++) {
            uint32_t a[4][4];
            int lrow = lane & 15, lcol = kt * 16 + (lane >> 4) * 8;
#pragma unroll
            for (int i = 0; i < 4; i++)
                ldsm_x4(a[i][0], a[i][1], a[i][2], a[i][3],
                        smem_u32(As[s] + (wm * 64 + i * 16 + lrow) * AS_STRIDE + lcol));
            uint32_t bb[4][2];
            int l = lane & 15;
#pragma unroll
            for (int j = 0; j < 4; j++)
                ldsm_x2_t(bb[j][0], bb[j][1],
                          smem_u32(Bs[s] + (kt * 16 + l) * BS_STRIDE + wn * 32 + j * 8));
#pragma unroll
            for (int i = 0; i < 4; i++)
#pragma unroll
                for (int j = 0; j < 4; j++)
                    mma16816(acc[i][j], a[i][0], a[i][1], a[i][2], a[i][3], bb[j][0], bb[j][1]);
        }
        if (k + 1 < KSTEPS) {
            int ns = s ^ 1;
            *(uint4*)(As[ns] + ar0 * AS_STRIDE + ac0) = a0;
            *(uint4*)(As[ns] + ar1 * AS_STRIDE + ac1) = a1;
            *(uint4*)(Bs[ns] + br * BS_STRIDE + bc)      = b0;
            *(uint4*)(Bs[ns] + br * BS_STRIDE + bc + 64) = b1;
            __syncthreads();
            s = ns;
        }
    }
#pragma unroll
    for (int i = 0; i < 4; i++)
#pragma unroll
        for (int j = 0; j < 4; j++) {
            int row = m0 + wm * 64 + i * 16 + (lane >> 2);
            int col = n0 + wn * 32 + j * 8 + (lane & 3) * 2;
            float bo0 = b_out[row];
            float bo1 = b_out[row + 8];
            float2 xr0 = *(const float2*)(x + ((size_t)b * D_SZ + row) * N_SZ + col);
            float2 xr1 = *(const float2*)(x + ((size_t)b * D_SZ + row + 8) * N_SZ + col);
            *(float2*)(out + ((size_t)b * D_SZ + row) * N_SZ + col) =
                make_float2(acc[i][j][0] + bo0 + xr0.x, acc[i][j][1] + bo0 + xr0.y);
            *(float2*)(out + ((size_t)b * D_SZ + row + 8) * N_SZ + col) =
                make_float2(acc[i][j][2] + bo1 + xr1.x, acc[i][j][3] + bo1 + xr1.y);
        }
}

// ---------------- launch ----------------------------------------------------
extern "C" void kernel_launch(void* const* d_in, const int* in_sizes, int n_in,
                              void* d_out, int out_size) {
    (void)in_sizes; (void)n_in; (void)out_size;
    const float* x     = (const float*)d_in[0];
    const float* gamma = (const float*)d_in[1];
    const float* beta  = (const float*)d_in[2];
    const float* w_qkv = (const float*)d_in[3];
    const float* w_out = (const float*)d_in[4];
    const float* b_out = (const float*)d_in[5];
    float* out = (float*)d_out;

    const int ln_smem = D_SZ * 33 * (int)sizeof(float);
    cudaFuncSetAttribute(k_lnxn, cudaFuncAttributeMaxDynamicSharedMemorySize, ln_smem);

    k_prep<<<(KV_M * D_SZ + 255) / 256, 256>>>(w_qkv);
    k_lnxn<<<dim3(N_SZ / 32, B_SZ), 256, ln_smem>>>(x, gamma, beta);
    k_gemm_kv<<<dim3(NTILES, KV_M / 128, B_SZ), 256>>>();
    k_combine<<<B_SZ * 512 / 8, 256>>>();
    k_ctx<<<dim3(8, HEADS, B_SZ), 256>>>();
    k_ctx_reduce<<<(B_SZ * HEADS * 64 * 64 + 255) / 256, 256>>>();
    k_w2<<<dim3(384 * 512 / 256, B_SZ), 256>>>(w_out);
    k_w3<<<dim3(3, 3, B_SZ), 256>>>(w_qkv);
    k_final<<<dim3(NTILES, 3, B_SZ), 256>>>(x, b_out, out);
}